// round 10
// baseline (speedup 1.0000x reference)
#include <cuda_runtime.h>
#include <cstdint>

#define LOCN  10000
#define DLOC  128
#define DST   64
#define DSUM  256
#define BB    64
#define SS    128
#define NIDX  (BB * SS)        // 8192 loc entries (with duplicates)
#define NBLK  1184             // 8 blocks/SM x 148 SMs, 64-thread blocks
#define HALF4 1250             // float4 per warp (2500 / 2 warps)

// Final Y = relu(A@W + b)*16 for claimed rows (5.12 MB).
__device__ float g_Y[(size_t)LOCN * DLOC];
__device__ int   g_flag[LOCN];     // epoch-tagged claims (never cleared)
__device__ int   g_work;           // work-stealing cursor over loc entries
__device__ int   g_epoch;          // bumped by gather kernel each launch

// ---------------------------------------------------------------------------
// Kernel 1: 64-thread blocks (2 warps). Prologue writes Y-independent output
// regions (st/ed/yt). Then blocks steal whole rows (one pop+claim per row,
// like round 8) but the TWO warps split the row's K-range — halving per-row
// latency and the tail quantization without extra traffic or atomics.
// Warp 0 dumps partial accs to smem; warp 1 combines + bias/relu/scale.
// ---------------------------------------------------------------------------
__global__ void __launch_bounds__(64, 8) spmm_kernel(
    const int*   __restrict__ loc,
    const int*   __restrict__ st,
    const int*   __restrict__ ed,
    const float* __restrict__ A,
    const float* __restrict__ W,
    const float* __restrict__ bias,
    const float* __restrict__ emb_st,
    const float* __restrict__ emb_ed,
    float4*      __restrict__ out)
{
    __shared__ float s_acc[DLOC];
    __shared__ int   s_widx, s_claimed, s_row;

    const int tid  = blockIdx.x * 64 + threadIdx.x;
    const int wid  = threadIdx.x >> 5;          // 0 or 1
    const int lane = threadIdx.x & 31;
    const int e    = g_epoch + 1;

    // ---------- Phase A: non-Y outputs (st / ed / yt), grid-stride --------
    {
        constexpr int N1V = NIDX * (DSUM / 4);      // 524288 (res region)
        constexpr int NJ  = NIDX * 48;              // 393216 non-Y float4
        const float4* __restrict__ stv = reinterpret_cast<const float4*>(emb_st);
        const float4* __restrict__ edv = reinterpret_cast<const float4*>(emb_ed);
        const float s = 16.0f;

        for (int j = tid; j < NJ; j += NBLK * 64) {
            const int token = j / 48;
            const int k     = j - token * 48;
            if (k < 16) {                       // st branch, d4 = 32+k
                float4 r = stv[st[token] * 16 + k];
                r.x *= s; r.y *= s; r.z *= s; r.w *= s;
                out[token * 64 + 32 + k] = r;
            } else if (k < 32) {                // ed branch
                float4 r = edv[ed[token] * 16 + (k - 16)];
                r.x *= s; r.y *= s; r.z *= s; r.w *= s;
                out[token * 64 + 32 + k] = r;
            } else {                            // yt region (NOT scaled)
                const int kk = k - 32;
                const int ss = token & (SS - 1);
                const int yt = (ss < SS - 1) ? st[token + 1] : 0;
                out[N1V + token * 16 + kk] = stv[yt * 16 + kk];
            }
        }
    }

    // ---------- Phase B: row stealing, 2-warp cooperative rows -------------
    constexpr int K   = 8;                     // float4 per lane per iter
    constexpr int VPI = 32 * K;                // 256 float4/warp/iter
    constexpr int NIT = (HALF4 + VPI - 1) / VPI; // 5
    const float4 Z = make_float4(0.f, 0.f, 0.f, 0.f);

    const float b0v = bias[lane];
    const float b1v = bias[lane + 32];
    const float b2v = bias[lane + 64];
    const float b3v = bias[lane + 96];

    for (;;) {
        if (threadIdx.x == 0) {
            const int widx = atomicAdd(&g_work, 1);
            int claimed = 0, row = 0;
            if (widx < NIDX) {
                row = __ldg(&loc[widx]);
                claimed = (atomicExch(&g_flag[row], e) != e);
            }
            s_widx = widx; s_claimed = claimed; s_row = row;
        }
        __syncthreads();
        const int widx    = s_widx;
        const int claimed = s_claimed;
        const int row     = s_row;
        __syncthreads();                 // protect s_* from next-pop overwrite
        if (widx >= NIDX) return;
        if (!claimed) continue;

        const float4* __restrict__ rp =
            reinterpret_cast<const float4*>(A + (size_t)row * LOCN);
        const int qstart = wid * HALF4;
        const int qend   = qstart + HALF4;

        float acc0 = 0.f, acc1 = 0.f, acc2 = 0.f, acc3 = 0.f;

        float4 cur[K], nxt[K];
        #pragma unroll
        for (int k = 0; k < K; ++k) {
            const int idx = qstart + lane + 32 * k;
            cur[k] = (idx < qend) ? __ldcs(&rp[idx]) : Z;
        }

        for (int it = 0; it < NIT; ++it) {
            if (it + 1 < NIT) {
                const int nbase = qstart + (it + 1) * VPI + lane;
                #pragma unroll
                for (int k = 0; k < K; ++k) {
                    const int idx = nbase + 32 * k;
                    nxt[k] = (idx < qend) ? __ldcs(&rp[idx]) : Z;
                }
            }

            #pragma unroll
            for (int k = 0; k < K; ++k) {
                const float4 v = cur[k];
                const bool nz = (v.x != 0.f) | (v.y != 0.f) |
                                (v.z != 0.f) | (v.w != 0.f);
                unsigned m = __ballot_sync(0xffffffffu, nz);
                while (m) {
                    const int j = __ffs(m) - 1;
                    m &= m - 1;
                    const float vx = __shfl_sync(0xffffffffu, v.x, j);
                    const float vy = __shfl_sync(0xffffffffu, v.y, j);
                    const float vz = __shfl_sync(0xffffffffu, v.z, j);
                    const float vw = __shfl_sync(0xffffffffu, v.w, j);
                    const int n0 = (qstart + it * VPI + k * 32 + j) * 4;

                    const float* __restrict__ Wr = W + (size_t)n0 * DLOC + lane;
                    if (vx != 0.f) {
                        acc0 = fmaf(vx, Wr[0],  acc0);
                        acc1 = fmaf(vx, Wr[32], acc1);
                        acc2 = fmaf(vx, Wr[64], acc2);
                        acc3 = fmaf(vx, Wr[96], acc3);
                    }
                    Wr += DLOC;
                    if (vy != 0.f) {
                        acc0 = fmaf(vy, Wr[0],  acc0);
                        acc1 = fmaf(vy, Wr[32], acc1);
                        acc2 = fmaf(vy, Wr[64], acc2);
                        acc3 = fmaf(vy, Wr[96], acc3);
                    }
                    Wr += DLOC;
                    if (vz != 0.f) {
                        acc0 = fmaf(vz, Wr[0],  acc0);
                        acc1 = fmaf(vz, Wr[32], acc1);
                        acc2 = fmaf(vz, Wr[64], acc2);
                        acc3 = fmaf(vz, Wr[96], acc3);
                    }
                    Wr += DLOC;
                    if (vw != 0.f) {
                        acc0 = fmaf(vw, Wr[0],  acc0);
                        acc1 = fmaf(vw, Wr[32], acc1);
                        acc2 = fmaf(vw, Wr[64], acc2);
                        acc3 = fmaf(vw, Wr[96], acc3);
                    }
                }
            }

            #pragma unroll
            for (int k = 0; k < K; ++k) cur[k] = nxt[k];
        }

        // Combine the two warps' partials; warp 1 writes the final row.
        if (wid == 0) {
            s_acc[lane]      = acc0;
            s_acc[lane + 32] = acc1;
            s_acc[lane + 64] = acc2;
            s_acc[lane + 96] = acc3;
        }
        __syncthreads();
        if (wid == 1) {
            const float s = 16.0f;
            float* __restrict__ y = g_Y + (size_t)row * DLOC + lane;
            y[0]  = fmaxf(acc0 + s_acc[lane]      + b0v, 0.f) * s;
            y[32] = fmaxf(acc1 + s_acc[lane + 32] + b1v, 0.f) * s;
            y[64] = fmaxf(acc2 + s_acc[lane + 64] + b2v, 0.f) * s;
            y[96] = fmaxf(acc3 + s_acc[lane + 96] + b3v, 0.f) * s;
        }
        __syncthreads();                 // protect s_acc before next row
    }
}

// ---------------------------------------------------------------------------
// Kernel 2: loc branch of the output (Y already has bias/relu/scale).
//   out[token*64 + d4] = Y[loc[token]][d4], d4 in [0,32) float4.
// Also resets bookkeeping for the next launch.
// ---------------------------------------------------------------------------
__global__ void __launch_bounds__(256) gather_loc_kernel(
    const int* __restrict__ loc,
    float4*    __restrict__ out)
{
    constexpr int NLV = NIDX * 32;               // 262144 float4
    const int idx = blockIdx.x * 256 + threadIdx.x;
    if (idx >= NLV) return;

    if (idx == 0) {
        g_epoch = g_epoch + 1;
        g_work  = 0;
    }

    const int bs = idx >> 5;
    const int d4 = idx & 31;
    const float4* __restrict__ Yv = reinterpret_cast<const float4*>(g_Y);
    out[bs * 64 + d4] = Yv[(size_t)loc[bs] * 32 + d4];
}

extern "C" void kernel_launch(void* const* d_in, const int* in_sizes, int n_in,
                              void* d_out, int out_size)
{
    const int*   loc    = (const int*)  d_in[0];
    const int*   st     = (const int*)  d_in[1];
    const int*   ed     = (const int*)  d_in[2];
    const float* A      = (const float*)d_in[3];
    const float* W_loc  = (const float*)d_in[4];
    const float* b_loc  = (const float*)d_in[5];
    const float* emb_st = (const float*)d_in[6];
    const float* emb_ed = (const float*)d_in[7];

    spmm_kernel<<<NBLK, 64>>>(loc, st, ed, A, W_loc, b_loc,
                              emb_st, emb_ed, (float4*)d_out);

    constexpr int nlv = NIDX * 32;
    gather_loc_kernel<<<nlv / 256, 256>>>(loc, (float4*)d_out);
}

// round 11
// speedup vs baseline: 1.0429x; 1.0429x over previous
#include <cuda_runtime.h>
#include <cstdint>

#define LOCN  10000
#define DLOC  128
#define DST   64
#define DSUM  256
#define BB    64
#define SS    128
#define NIDX  (BB * SS)        // 8192 loc entries (with duplicates)
#define NBLK  296              // 2 blocks/SM x 148 SMs

// Final Y = relu(A@W + b)*16 for claimed rows (5.12 MB).
__device__ float g_Y[(size_t)LOCN * DLOC];
__device__ int   g_flag[LOCN];     // epoch-tagged claims (never cleared)
__device__ int   g_work;           // work-stealing cursor over loc entries
__device__ int   g_epoch;          // bumped by gather kernel each launch

// ---------------------------------------------------------------------------
// Kernel 1: prologue writes Y-independent output regions (st/ed/yt), then
// persistent warps steal whole rows (round-8 proven core) with PREFETCHED
// pops: lane 0 issues the next atomicAdd+claim before streaming the current
// row; the warp broadcasts it only when the row is done, hiding ~1000 cyc
// of atomic latency per row. Per row: 8 float4/lane/iter + next-iter
// prefetch (16 loads in flight per lane).
// ---------------------------------------------------------------------------
__global__ void __launch_bounds__(256, 2) spmm_kernel(
    const int*   __restrict__ loc,
    const int*   __restrict__ st,
    const int*   __restrict__ ed,
    const float* __restrict__ A,
    const float* __restrict__ W,
    const float* __restrict__ bias,
    const float* __restrict__ emb_st,
    const float* __restrict__ emb_ed,
    float4*      __restrict__ out)
{
    const int tid  = blockIdx.x * 256 + threadIdx.x;
    const int lane = threadIdx.x & 31;
    const int e    = g_epoch + 1;

    // ---------- Phase A: non-Y outputs (st / ed / yt), grid-stride --------
    {
        constexpr int N1V = NIDX * (DSUM / 4);      // 524288 (res region)
        constexpr int NJ  = NIDX * 48;              // 393216 non-Y float4
        const float4* __restrict__ stv = reinterpret_cast<const float4*>(emb_st);
        const float4* __restrict__ edv = reinterpret_cast<const float4*>(emb_ed);
        const float s = 16.0f;

        for (int j = tid; j < NJ; j += NBLK * 256) {
            const int token = j / 48;
            const int k     = j - token * 48;
            if (k < 16) {                       // st branch, d4 = 32+k
                float4 r = stv[st[token] * 16 + k];
                r.x *= s; r.y *= s; r.z *= s; r.w *= s;
                out[token * 64 + 32 + k] = r;
            } else if (k < 32) {                // ed branch
                float4 r = edv[ed[token] * 16 + (k - 16)];
                r.x *= s; r.y *= s; r.z *= s; r.w *= s;
                out[token * 64 + 32 + k] = r;
            } else {                            // yt region (NOT scaled)
                const int kk = k - 32;
                const int ss = token & (SS - 1);
                const int yt = (ss < SS - 1) ? st[token + 1] : 0;
                out[N1V + token * 16 + kk] = stv[yt * 16 + kk];
            }
        }
    }

    // ---------- Phase B: whole-row work stealing with pop prefetch ---------
    constexpr int NV4   = LOCN / 4;                    // 2500
    constexpr int K     = 8;                           // float4/lane/iter
    constexpr int VPI   = 32 * K;                      // 256 float4/warp/iter
    constexpr int NITER = (NV4 + VPI - 1) / VPI;       // 10
    const float4 Z = make_float4(0.f, 0.f, 0.f, 0.f);

    const float b0v = bias[lane];
    const float b1v = bias[lane + 32];
    const float b2v = bias[lane + 64];
    const float b3v = bias[lane + 96];

    // lane-0 private prefetched pop state
    int p_widx = NIDX, p_row = 0, p_claimed = 0;
    if (lane == 0) {
        p_widx = atomicAdd(&g_work, 1);
        p_claimed = 0;
        if (p_widx < NIDX) {
            p_row = __ldg(&loc[p_widx]);
            p_claimed = (atomicExch(&g_flag[p_row], e) != e);
        }
    }

    for (;;) {
        // Broadcast the (prefetched) pop.
        const int widx    = __shfl_sync(0xffffffffu, p_widx, 0);
        const int claimed = __shfl_sync(0xffffffffu, p_claimed, 0);
        const int row     = __shfl_sync(0xffffffffu, p_row, 0);
        if (widx >= NIDX) return;

        if (!claimed) {                  // duplicate: synchronous re-pop
            if (lane == 0) {
                p_widx = atomicAdd(&g_work, 1);
                p_claimed = 0;
                if (p_widx < NIDX) {
                    p_row = __ldg(&loc[p_widx]);
                    p_claimed = (atomicExch(&g_flag[p_row], e) != e);
                }
            }
            continue;
        }

        // Prefetch the NEXT pop now; broadcast happens after this row's work.
        if (lane == 0) {
            p_widx = atomicAdd(&g_work, 1);
            p_claimed = 0;
            if (p_widx < NIDX) {
                p_row = __ldg(&loc[p_widx]);
                p_claimed = (atomicExch(&g_flag[p_row], e) != e);
            }
        }

        const float4* __restrict__ rp =
            reinterpret_cast<const float4*>(A + (size_t)row * LOCN);

        float acc0 = 0.f, acc1 = 0.f, acc2 = 0.f, acc3 = 0.f;

        float4 cur[K], nxt[K];
        #pragma unroll
        for (int k = 0; k < K; ++k) {
            const int idx = lane + 32 * k;
            cur[k] = (idx < NV4) ? __ldcs(&rp[idx]) : Z;
        }

        for (int it = 0; it < NITER; ++it) {
            if (it + 1 < NITER) {
                const int nbase = (it + 1) * VPI + lane;
                #pragma unroll
                for (int k = 0; k < K; ++k) {
                    const int idx = nbase + 32 * k;
                    nxt[k] = (idx < NV4) ? __ldcs(&rp[idx]) : Z;
                }
            }

            #pragma unroll
            for (int k = 0; k < K; ++k) {
                const float4 v = cur[k];
                const bool nz = (v.x != 0.f) | (v.y != 0.f) |
                                (v.z != 0.f) | (v.w != 0.f);
                unsigned m = __ballot_sync(0xffffffffu, nz);
                while (m) {
                    const int j = __ffs(m) - 1;
                    m &= m - 1;
                    const float vx = __shfl_sync(0xffffffffu, v.x, j);
                    const float vy = __shfl_sync(0xffffffffu, v.y, j);
                    const float vz = __shfl_sync(0xffffffffu, v.z, j);
                    const float vw = __shfl_sync(0xffffffffu, v.w, j);
                    const int n0 = (it * VPI + k * 32 + j) * 4;

                    const float* __restrict__ Wr = W + (size_t)n0 * DLOC + lane;
                    if (vx != 0.f) {
                        acc0 = fmaf(vx, Wr[0],  acc0);
                        acc1 = fmaf(vx, Wr[32], acc1);
                        acc2 = fmaf(vx, Wr[64], acc2);
                        acc3 = fmaf(vx, Wr[96], acc3);
                    }
                    Wr += DLOC;
                    if (vy != 0.f) {
                        acc0 = fmaf(vy, Wr[0],  acc0);
                        acc1 = fmaf(vy, Wr[32], acc1);
                        acc2 = fmaf(vy, Wr[64], acc2);
                        acc3 = fmaf(vy, Wr[96], acc3);
                    }
                    Wr += DLOC;
                    if (vz != 0.f) {
                        acc0 = fmaf(vz, Wr[0],  acc0);
                        acc1 = fmaf(vz, Wr[32], acc1);
                        acc2 = fmaf(vz, Wr[64], acc2);
                        acc3 = fmaf(vz, Wr[96], acc3);
                    }
                    Wr += DLOC;
                    if (vw != 0.f) {
                        acc0 = fmaf(vw, Wr[0],  acc0);
                        acc1 = fmaf(vw, Wr[32], acc1);
                        acc2 = fmaf(vw, Wr[64], acc2);
                        acc3 = fmaf(vw, Wr[96], acc3);
                    }
                }
            }

            #pragma unroll
            for (int k = 0; k < K; ++k) cur[k] = nxt[k];
        }

        const float s = 16.0f;
        float* __restrict__ y = g_Y + (size_t)row * DLOC + lane;
        y[0]  = fmaxf(acc0 + b0v, 0.f) * s;
        y[32] = fmaxf(acc1 + b1v, 0.f) * s;
        y[64] = fmaxf(acc2 + b2v, 0.f) * s;
        y[96] = fmaxf(acc3 + b3v, 0.f) * s;
    }
}

// ---------------------------------------------------------------------------
// Kernel 2: loc branch only (Y already has bias/relu/scale):
//   out[token*64 + d4] = Y[loc[token]][d4], d4 in [0,32) float4.
// Also resets bookkeeping for the next launch.
// ---------------------------------------------------------------------------
__global__ void __launch_bounds__(256) gather_loc_kernel(
    const int* __restrict__ loc,
    float4*    __restrict__ out)
{
    constexpr int NLV = NIDX * 32;               // 262144 float4
    const int idx = blockIdx.x * 256 + threadIdx.x;
    if (idx >= NLV) return;

    if (idx == 0) {
        g_epoch = g_epoch + 1;
        g_work  = 0;
    }

    const int bs = idx >> 5;
    const int d4 = idx & 31;
    const float4* __restrict__ Yv = reinterpret_cast<const float4*>(g_Y);
    out[bs * 64 + d4] = Yv[(size_t)loc[bs] * 32 + d4];
}

extern "C" void kernel_launch(void* const* d_in, const int* in_sizes, int n_in,
                              void* d_out, int out_size)
{
    const int*   loc    = (const int*)  d_in[0];
    const int*   st     = (const int*)  d_in[1];
    const int*   ed     = (const int*)  d_in[2];
    const float* A      = (const float*)d_in[3];
    const float* W_loc  = (const float*)d_in[4];
    const float* b_loc  = (const float*)d_in[5];
    const float* emb_st = (const float*)d_in[6];
    const float* emb_ed = (const float*)d_in[7];

    spmm_kernel<<<NBLK, 256>>>(loc, st, ed, A, W_loc, b_loc,
                               emb_st, emb_ed, (float4*)d_out);

    constexpr int nlv = NIDX * 32;
    gather_loc_kernel<<<nlv / 256, 256>>>(loc, (float4*)d_out);
}